// round 16
// baseline (speedup 1.0000x reference)
#include <cuda_runtime.h>
#include <math.h>

#define T_LEN  480000
#define B_ROWS 64
#define YSPLIT 16
#define B_SUB  (B_ROWS / YSPLIT)          // 4 batches per block
#define NTHR   256

// RN(1/16000): matches XLA's divide->multiply-by-reciprocal rewrite.
// Load-bearing for correctness (round-4 win) -- do not change.
#define INV_SR 6.25e-5f

// ---------------------------------------------------------------------------
// Sine = exact Cody-Waite mod-2pi reduction + MUFU sin on r in [-pi, pi].
// Validated rounds 13-15 (rel_err 5.47e-4). BIT-IDENTICAL -- do not change.
// ---------------------------------------------------------------------------
__device__ __forceinline__ float sin_fast(float x)
{
    const float MAGIC = 12582912.0f;                   // 1.5 * 2^23
    float jf = __fmaf_rn(x, 0.15915494309189533577f, MAGIC);  // round(x/2pi)
    float n  = __fsub_rn(jf, MAGIC);

    float r = __fmaf_rn(n, -6.28318548202514648438f, x);
    r = __fmaf_rn(n, 1.74845560007442631e-7f, r);      // +n*(hi - 2pi)

    float s;
    asm("sin.approx.f32 %0, %1;" : "=f"(s) : "f"(r));  // MUFU on reduced arg
    return s;
}

// One (i,b) sample. CHECK=false: i >= 1024 > 800 >= delay proves rp >= 0 and
// il >= 0; skip the clamp + select.
template<bool CHECK>
__device__ __forceinline__ float chorus_sample(
    const float* __restrict__ row, int i, float posf, float t, float4 p)
{
    // arg = ((2*pi)*rate) * t -- exact reference f32 op order (p.x = 2pi*rate).
    const float arg = __fmul_rn(p.x, t);
    const float lfo = sin_fast(arg);

    // delay = cds + ((lfo*depth)*cds) -- exact ref rounding order.
    // Upper clip dead (cds <= 400, |lfo*depth| <= 1 -> delay <= 800 = bound;
    // equality clamp is identity -- bitwise-validated round 15).
    float delay = __fadd_rn(p.z, __fmul_rn(__fmul_rn(lfo, p.y), p.z));
    delay = fmaxf(delay, 1.0f);

    const float rp = __fsub_rn(posf, delay);           // ref's f32 quantization
    int il = __float2int_rd(rp);
    if (CHECK) il = max(il, 0);
    const float frac = __fsub_rn(rp, floorf(rp));

    const float a0 = __ldg(row + il);
    const float a1 = __ldg(row + il + 1);
    const float x  = __ldg(row + i);

    float delayed = __fmaf_rn(frac, __fsub_rn(a1, a0), a0);
    if (CHECK) delayed = (rp >= 0.0f) ? delayed : 0.0f;

    // x*(1-m) + d*m == x + m*(d-x); ±1ulp direct error, un-amplified.
    return __fmaf_rn(p.w, __fsub_rn(delayed, x), x);
}

template<bool CHECK>
__device__ __forceinline__ void chorus_body(
    const float* __restrict__ audio, float* __restrict__ out,
    const float4* __restrict__ s_p, int i)
{
    const float posf = (float)i;                       // exact (i < 2^24)
    const float t = __fmul_rn(posf, INV_SR);           // XLA reciprocal-mul

    const float* row  = audio;
    float*       orow = out;

    // 4 batches per block (blockIdx.y split): per-SM gather working set
    // = 8 blocks x 4 rows x 4.2KB ~ 134KB < 228KB L1 -> gathers L1-hit
    // instead of ~240-cycle L2 round trips (round-15 issue stall source).
    // Full unroll of 4 = the proven round-13 unroll depth (no L1tex queue
    // overflow from front-batched LDGs).
    #pragma unroll
    for (int b = 0; b < B_SUB; ++b, row += T_LEN, orow += T_LEN) {
        const float4 p = s_p[b];                       // one LDS.128 broadcast
        orow[i] = chorus_sample<CHECK>(row, i, posf, t, p);
    }
}

__global__ __launch_bounds__(NTHR, 8)   // force <=32 regs -> 8 blocks/SM
void chorus_kernel(const float* __restrict__ audio,
                   const float* __restrict__ rate_hz,
                   const float* __restrict__ depth,
                   const float* __restrict__ centre_ms,
                   const float* __restrict__ mix,
                   float* __restrict__ out)
{
    __shared__ float4 s_p[B_SUB];                      // {2pi*rate, depth, cds, mix}

    const int b_base = blockIdx.y * B_SUB;
    const float TWO_PI_F = 6.28318530717958647692f;    // f32 = 0x40C90FDB
    if (threadIdx.x < B_SUB) {
        const int b = b_base + threadIdx.x;
        float4 p;
        p.x = __fmul_rn(TWO_PI_F, __ldg(rate_hz + b));
        p.y = __ldg(depth + b);
        p.z = __fmul_rn(__ldg(centre_ms + b), 16.0f);
        p.w = __ldg(mix + b);
        s_p[threadIdx.x] = p;
    }
    __syncthreads();

    const int i = blockIdx.x * NTHR + threadIdx.x;
    if (i >= T_LEN) return;

    const float* audio_h = audio + (size_t)b_base * T_LEN;
    float*       out_h   = out   + (size_t)b_base * T_LEN;

    // Block-uniform specialization: bx >= 4 -> i >= 1024 -> rp, il in range.
    if (blockIdx.x >= 4) chorus_body<false>(audio_h, out_h, s_p, i);
    else                 chorus_body<true >(audio_h, out_h, s_p, i);
}

extern "C" void kernel_launch(void* const* d_in, const int* in_sizes, int n_in,
                              void* d_out, int out_size)
{
    // metadata order: audio, rate_hz, depth, centre_delay_ms, feedback(unused), mix
    const float* audio     = (const float*)d_in[0];
    const float* rate_hz   = (const float*)d_in[1];
    const float* depth     = (const float*)d_in[2];
    const float* centre_ms = (const float*)d_in[3];
    const float* mix       = (const float*)d_in[5];
    float* out = (float*)d_out;

    (void)in_sizes; (void)n_in; (void)out_size;

    dim3 grid((T_LEN + NTHR - 1) / NTHR, YSPLIT);      // 1875 x 16
    chorus_kernel<<<grid, NTHR>>>(audio, rate_hz, depth, centre_ms, mix, out);
}